// round 1
// baseline (speedup 1.0000x reference)
#include <cuda_runtime.h>
#include <stdint.h>

// Problem constants (shape-specialized registry problem)
#define NMAX 100000
#define EMAX 3200000
#define HDIM 64

// Scratch (device globals; no allocation allowed)
__device__ float g_deg[NMAX];
__device__ float g_dinv[NMAX];
__device__ float g_h[NMAX * HDIM];     // GEMM output of current layer
__device__ float g_agg[NMAX * HDIM];   // aggregation buffer
__device__ int   g_src[EMAX];
__device__ int   g_dst[EMAX];
__device__ float g_norm[EMAX];
__device__ int   g_is64;

// ---------------------------------------------------------------------------
// Detect whether edge_index is int64 or int32.
// If int64: every 8-byte word is a valid index in [0, n).
// If int32: an 8-byte word packs two indices -> value ~ idx + next*2^32, huge.
// P(false int64 detect) = P(64 consecutive high words all zero) ~ (1e-5)^64.
__global__ void k_detect(const void* ei, int n) {
    if (blockIdx.x == 0 && threadIdx.x == 0) {
        const long long* p = (const long long*)ei;
        int ok = 1;
        for (int i = 0; i < 64; i++) {
            long long v = p[i];
            if (v < 0 || v >= (long long)n) { ok = 0; break; }
        }
        g_is64 = ok;
    }
}

// Convert edge indices to int32 scratch arrays (src row 0, dst row 1).
__global__ void k_convert(const void* ei, int e) {
    int i = blockIdx.x * blockDim.x + threadIdx.x;
    if (i >= e) return;
    if (g_is64) {
        const long long* p = (const long long*)ei;
        g_src[i] = (int)p[i];
        g_dst[i] = (int)p[e + i];
    } else {
        const int* p = (const int*)ei;
        g_src[i] = p[i];
        g_dst[i] = p[e + i];
    }
}

__global__ void k_init_deg(int n) {
    int i = blockIdx.x * blockDim.x + threadIdx.x;
    if (i < n) g_deg[i] = 1.0f;  // self-loop
}

__global__ void k_accum_deg(int e) {
    int i = blockIdx.x * blockDim.x + threadIdx.x;
    if (i < e) atomicAdd(&g_deg[g_dst[i]], 1.0f);
}

__global__ void k_dinv(int n) {
    int i = blockIdx.x * blockDim.x + threadIdx.x;
    if (i < n) g_dinv[i] = rsqrtf(g_deg[i]);  // deg >= 1 always
}

__global__ void k_norm(int e) {
    int i = blockIdx.x * blockDim.x + threadIdx.x;
    if (i < e) g_norm[i] = g_dinv[g_src[i]] * g_dinv[g_dst[i]];
}

// ---------------------------------------------------------------------------
// Tiled GEMM: Y[n, 64] = X[n, FIN] @ W[FIN, 64]   (optional relu on X)
// blockDim (16,16); thread (tx,ty): node tile row ty, outputs tx*4..tx*4+3.
template <int FIN, bool RELU_IN>
__global__ void k_gemm(const float* __restrict__ X, const float* __restrict__ W,
                       float* __restrict__ Y, int n) {
    __shared__ float Ws[FIN * HDIM];
    __shared__ float Xs[16][FIN];
    const int tid = threadIdx.y * 16 + threadIdx.x;

    for (int i = tid; i < FIN * HDIM; i += 256) Ws[i] = W[i];

    const int numTiles = (n + 15) >> 4;
    for (int tile = blockIdx.x; tile < numTiles; tile += gridDim.x) {
        const int base = tile << 4;
        __syncthreads();
        // load 16 node rows
        for (int i = tid; i < 16 * FIN; i += 256) {
            int node = base + i / FIN;
            float v = 0.0f;
            if (node < n) v = X[(long long)node * FIN + (i % FIN)];
            if (RELU_IN) v = fmaxf(v, 0.0f);
            Xs[i / FIN][i % FIN] = v;
        }
        __syncthreads();

        float a0 = 0.f, a1 = 0.f, a2 = 0.f, a3 = 0.f;
        #pragma unroll 8
        for (int k = 0; k < FIN; k++) {
            float xv = Xs[threadIdx.y][k];
            const float4 w = *(const float4*)&Ws[k * HDIM + threadIdx.x * 4];
            a0 = fmaf(xv, w.x, a0);
            a1 = fmaf(xv, w.y, a1);
            a2 = fmaf(xv, w.z, a2);
            a3 = fmaf(xv, w.w, a3);
        }
        int node = base + threadIdx.y;
        if (node < n) {
            *(float4*)&Y[(long long)node * HDIM + threadIdx.x * 4] =
                make_float4(a0, a1, a2, a3);
        }
    }
}

// agg[v][f] = h[v][f] * dinv[v]^2 + b[f]     (self-loop contribution + bias)
__global__ void k_init_agg(const float* __restrict__ b, int n) {
    int i = blockIdx.x * blockDim.x + threadIdx.x;
    if (i >= n * HDIM) return;
    int v = i >> 6;
    int f = i & 63;
    float di = g_dinv[v];
    g_agg[i] = g_h[i] * di * di + b[f];
}

// Edge scatter: 16 lanes per edge, float4 gather + red.global.add.v4.f32
__global__ void k_scatter(int e) {
    long long gid = (long long)blockIdx.x * blockDim.x + threadIdx.x;
    int edge = (int)(gid >> 4);
    int sub  = (int)(gid & 15);
    if (edge >= e) return;
    int s = g_src[edge];
    int d = g_dst[edge];
    float nrm = g_norm[edge];
    const float4 v = *(const float4*)&g_h[(long long)s * HDIM + sub * 4];
    float* a = &g_agg[(long long)d * HDIM + sub * 4];
    asm volatile("red.global.add.v4.f32 [%0], {%1,%2,%3,%4};"
                 :: "l"(a), "f"(v.x * nrm), "f"(v.y * nrm),
                    "f"(v.z * nrm), "f"(v.w * nrm)
                 : "memory");
}

// out[v] = relu(agg[v]) . Wlin + blin   — one warp per node
__global__ void k_final(const float* __restrict__ Wlin,
                        const float* __restrict__ blin,
                        float* __restrict__ out, int n) {
    int gid = blockIdx.x * blockDim.x + threadIdx.x;
    int node = gid >> 5;
    int lane = gid & 31;
    if (node >= n) return;
    float2 v = *(const float2*)&g_agg[(long long)node * HDIM + lane * 2];
    float2 w = *(const float2*)&Wlin[lane * 2];
    float s = fmaxf(v.x, 0.f) * w.x + fmaxf(v.y, 0.f) * w.y;
    #pragma unroll
    for (int off = 16; off > 0; off >>= 1)
        s += __shfl_xor_sync(0xFFFFFFFFu, s, off);
    if (lane == 0) out[node] = s + blin[0];
}

// ---------------------------------------------------------------------------
extern "C" void kernel_launch(void* const* d_in, const int* in_sizes, int n_in,
                              void* d_out, int out_size) {
    const float* x    = (const float*)d_in[0];
    const void*  ei   = d_in[1];
    const float* W1   = (const float*)d_in[2];
    const float* b1   = (const float*)d_in[3];
    const float* W2   = (const float*)d_in[4];
    const float* b2   = (const float*)d_in[5];
    const float* Wlin = (const float*)d_in[6];
    const float* blin = (const float*)d_in[7];

    const int FIN = in_sizes[2] / HDIM;       // 128
    const int n   = in_sizes[0] / FIN;        // 100000
    const int e   = in_sizes[1] / 2;          // 3200000

    float* hbuf;  cudaGetSymbolAddress((void**)&hbuf, g_h);
    float* abuf;  cudaGetSymbolAddress((void**)&abuf, g_agg);
    (void)hbuf; (void)abuf;

    const int T = 256;
    const int nb_n   = (n + T - 1) / T;
    const int nb_e   = (e + T - 1) / T;
    const int nb_nh  = (n * HDIM + T - 1) / T;
    const int nb_sc  = (int)(((long long)e * 16 + T - 1) / T);
    const int nb_fin = (int)(((long long)n * 32 + T - 1) / T);

    // Graph normalization (once, reused by both layers)
    k_detect<<<1, 32>>>(ei, n);
    k_convert<<<nb_e, T>>>(ei, e);
    k_init_deg<<<nb_n, T>>>(n);
    k_accum_deg<<<nb_e, T>>>(e);
    k_dinv<<<nb_n, T>>>(n);
    k_norm<<<nb_e, T>>>(e);

    // Layer 1: h = x @ W1 ; agg = selfloop + bias ; scatter edges
    k_gemm<128, false><<<1480, dim3(16, 16)>>>(x, W1, hbuf, n);
    k_init_agg<<<nb_nh, T>>>(b1, n);
    k_scatter<<<nb_sc, T>>>(e);

    // Layer 2: h = relu(agg) @ W2 ; agg = selfloop + bias ; scatter edges
    k_gemm<64, true><<<1480, dim3(16, 16)>>>(abuf, W2, hbuf, n);
    k_init_agg<<<nb_nh, T>>>(b2, n);
    k_scatter<<<nb_sc, T>>>(e);

    // Head: out = relu(agg) @ Wlin + blin
    k_final<<<nb_fin, T>>>(Wlin, blin, (float*)d_out, n);
}

// round 2
// speedup vs baseline: 1.7473x; 1.7473x over previous
#include <cuda_runtime.h>
#include <stdint.h>

#define NMAX 100000
#define EMAX 3200000
#define HDIM 64

// ---------------- device scratch (no allocation allowed) -------------------
__device__ __align__(256) float g_h[NMAX * HDIM];    // GEMM out (pre-scaled by dinv)
__device__ __align__(256) float g_agg[NMAX * HDIM];  // aggregation result (pre dinv_d)
__device__ float g_dinv[NMAX];
__device__ int   g_cnt[NMAX];        // in-degree (excl self-loop)
__device__ int   g_off[NMAX + 1];    // CSR-by-dst offsets
__device__ int   g_cur[NMAX];        // scatter cursors
__device__ int   g_bsum[128];        // scan block sums
__device__ int   g_src[EMAX];
__device__ int   g_dst[EMAX];
__device__ int   g_ssrc[EMAX];       // src sorted by dst
__device__ int   g_is64;

// ---------------------------------------------------------------------------
// int64 vs int32 edge_index detection (reads 64 words; false positive ~0)
__global__ void k_detect(const void* ei, int n) {
    if (threadIdx.x == 0) {
        const long long* p = (const long long*)ei;
        int ok = 1;
        for (int i = 0; i < 64; i++) {
            long long v = p[i];
            if (v < 0 || v >= (long long)n) { ok = 0; break; }
        }
        g_is64 = ok;
    }
}

// Convert to int32 + histogram of dst (in-degree)
__global__ void k_convert_hist(const void* ei, int e) {
    int i = blockIdx.x * blockDim.x + threadIdx.x;
    if (i >= e) return;
    int s, d;
    if (g_is64) {
        const long long* p = (const long long*)ei;
        s = (int)p[i];
        d = (int)p[e + i];
    } else {
        const int* p = (const int*)ei;
        s = p[i];
        d = p[e + i];
    }
    g_src[i] = s;
    g_dst[i] = d;
    atomicAdd(&g_cnt[d], 1);
}

// ----------------------- hierarchical exclusive scan -----------------------
// pass 1: blocks of 1024 items (256 thr x 4), write in-block exclusive + sums
__global__ void k_scan1(int n) {
    __shared__ int wsum[8];
    const int t = threadIdx.x;
    const int base = blockIdx.x * 1024 + t * 4;
    int v0 = (base + 0 < n) ? g_cnt[base + 0] : 0;
    int v1 = (base + 1 < n) ? g_cnt[base + 1] : 0;
    int v2 = (base + 2 < n) ? g_cnt[base + 2] : 0;
    int v3 = (base + 3 < n) ? g_cnt[base + 3] : 0;
    int tsum = v0 + v1 + v2 + v3;
    int lane = t & 31, wid = t >> 5;
    int x = tsum;
    #pragma unroll
    for (int o = 1; o < 32; o <<= 1) {
        int y = __shfl_up_sync(0xFFFFFFFFu, x, o);
        if (lane >= o) x += y;
    }
    if (lane == 31) wsum[wid] = x;
    __syncthreads();
    if (wid == 0) {
        int ws = (lane < 8) ? wsum[lane] : 0;
        #pragma unroll
        for (int o = 1; o < 8; o <<= 1) {
            int y = __shfl_up_sync(0xFFFFFFFFu, ws, o);
            if (lane >= o) ws += y;
        }
        if (lane < 8) wsum[lane] = ws;
    }
    __syncthreads();
    int excl = x - tsum + (wid ? wsum[wid - 1] : 0);
    if (base + 0 < n) g_off[base + 0] = excl;           excl += v0;
    if (base + 1 < n) g_off[base + 1] = excl;           excl += v1;
    if (base + 2 < n) g_off[base + 2] = excl;           excl += v2;
    if (base + 3 < n) g_off[base + 3] = excl;
    if (t == 0) g_bsum[blockIdx.x] = wsum[7];
}

// pass 2: scan the (<=128) block sums in one block; also set g_off[n]=E
__global__ void k_scan2(int nb, int n) {
    __shared__ int s[128];
    int t = threadIdx.x;
    int own = (t < nb) ? g_bsum[t] : 0;
    s[t] = own;
    __syncthreads();
    #pragma unroll
    for (int o = 1; o < 128; o <<= 1) {
        int v = (t >= o) ? s[t - o] : 0;
        __syncthreads();
        s[t] += v;
        __syncthreads();
    }
    if (t < nb) g_bsum[t] = s[t] - own;   // exclusive
    if (t == nb - 1) g_off[n] = s[t];     // total = E
}

// pass 3: add block prefix; init cursors; dinv = rsqrt(deg_incl_selfloop)
__global__ void k_scan3(int n) {
    int i = blockIdx.x * blockDim.x + threadIdx.x;
    if (i >= n) return;
    int o = g_off[i] + g_bsum[i >> 10];
    g_off[i] = o;
    g_cur[i] = o;
    g_dinv[i] = rsqrtf((float)(g_cnt[i] + 1));
}

// scatter edge srcs into dst-sorted order
__global__ void k_scatter_idx(int e) {
    int i = blockIdx.x * blockDim.x + threadIdx.x;
    if (i >= e) return;
    int pos = atomicAdd(&g_cur[g_dst[i]], 1);
    g_ssrc[pos] = g_src[i];
}

// ---------------------------------------------------------------------------
// Tiled GEMM: Y[n,64] = f(X)[n,FIN] @ W[FIN,64], epilogue scale by dinv[node].
// FOLD: input element = relu(X * dinv[node] + b[k])  (consumer-side fold)
template <int FIN, bool FOLD>
__global__ void __launch_bounds__(256) k_gemm(const float* __restrict__ X,
                                              const float* __restrict__ W,
                                              const float* __restrict__ b,
                                              float* __restrict__ Y, int n) {
    __shared__ float Ws[FIN * HDIM];
    __shared__ float Xs[16][FIN];
    __shared__ float bs[HDIM];
    const int tid = threadIdx.y * 16 + threadIdx.x;

    for (int i = tid; i < FIN * HDIM; i += 256) Ws[i] = W[i];
    if (FOLD) { if (tid < FIN) bs[tid] = b[tid]; }

    const int numTiles = (n + 15) >> 4;
    for (int tile = blockIdx.x; tile < numTiles; tile += gridDim.x) {
        const int base = tile << 4;
        __syncthreads();
        for (int i = tid; i < 16 * FIN; i += 256) {
            int node = base + i / FIN;
            int k = i % FIN;
            float v = 0.0f;
            if (node < n) {
                v = X[(size_t)node * FIN + k];
                if (FOLD) v = fmaxf(fmaf(v, g_dinv[node], bs[k]), 0.0f);
            }
            Xs[i / FIN][k] = v;
        }
        __syncthreads();

        float a0 = 0.f, a1 = 0.f, a2 = 0.f, a3 = 0.f;
        #pragma unroll 8
        for (int k = 0; k < FIN; k++) {
            float xv = Xs[threadIdx.y][k];
            const float4 w = *(const float4*)&Ws[k * HDIM + threadIdx.x * 4];
            a0 = fmaf(xv, w.x, a0);
            a1 = fmaf(xv, w.y, a1);
            a2 = fmaf(xv, w.z, a2);
            a3 = fmaf(xv, w.w, a3);
        }
        int node = base + threadIdx.y;
        if (node < n) {
            float di = g_dinv[node];
            *(float4*)&Y[(size_t)node * HDIM + threadIdx.x * 4] =
                make_float4(a0 * di, a1 * di, a2 * di, a3 * di);
        }
    }
}

// ---------------------------------------------------------------------------
// Aggregation: one warp per dst node, contiguous src segment, NO atomics.
// acc = h'[self] + sum h'[src];  stores pre-dinv_d sum (consumer folds rest).
__global__ void __launch_bounds__(256) k_aggregate(int n) {
    int w = (blockIdx.x * blockDim.x + threadIdx.x) >> 5;
    int lane = threadIdx.x & 31;
    if (w >= n) return;
    int e = g_off[w], e1 = g_off[w + 1];
    const size_t fo = (size_t)lane * 2;
    float2 acc = *(const float2*)&g_h[(size_t)w * HDIM + fo];

    for (; e + 4 <= e1; e += 4) {
        int sA = __ldg(&g_ssrc[e + 0]);
        int sB = __ldg(&g_ssrc[e + 1]);
        int sC = __ldg(&g_ssrc[e + 2]);
        int sD = __ldg(&g_ssrc[e + 3]);
        float2 vA = *(const float2*)&g_h[(size_t)sA * HDIM + fo];
        float2 vB = *(const float2*)&g_h[(size_t)sB * HDIM + fo];
        float2 vC = *(const float2*)&g_h[(size_t)sC * HDIM + fo];
        float2 vD = *(const float2*)&g_h[(size_t)sD * HDIM + fo];
        acc.x += vA.x + vB.x + vC.x + vD.x;
        acc.y += vA.y + vB.y + vC.y + vD.y;
    }
    for (; e < e1; e++) {
        int s = __ldg(&g_ssrc[e]);
        float2 v = *(const float2*)&g_h[(size_t)s * HDIM + fo];
        acc.x += v.x;
        acc.y += v.y;
    }
    *(float2*)&g_agg[(size_t)w * HDIM + fo] = acc;
}

// out[v] = relu(aggpre[v]*dinv[v] + b2) . Wlin + blin  — warp per node
__global__ void k_final(const float* __restrict__ b2,
                        const float* __restrict__ Wlin,
                        const float* __restrict__ blin,
                        float* __restrict__ out, int n) {
    int gid = blockIdx.x * blockDim.x + threadIdx.x;
    int node = gid >> 5;
    int lane = gid & 31;
    if (node >= n) return;
    float di = g_dinv[node];
    float2 v = *(const float2*)&g_agg[(size_t)node * HDIM + lane * 2];
    float2 bb = *(const float2*)&b2[lane * 2];
    float2 w = *(const float2*)&Wlin[lane * 2];
    float s = fmaxf(fmaf(v.x, di, bb.x), 0.f) * w.x +
              fmaxf(fmaf(v.y, di, bb.y), 0.f) * w.y;
    #pragma unroll
    for (int off = 16; off > 0; off >>= 1)
        s += __shfl_xor_sync(0xFFFFFFFFu, s, off);
    if (lane == 0) out[node] = s + blin[0];
}

// ---------------------------------------------------------------------------
extern "C" void kernel_launch(void* const* d_in, const int* in_sizes, int n_in,
                              void* d_out, int out_size) {
    const float* x    = (const float*)d_in[0];
    const void*  ei   = d_in[1];
    const float* W1   = (const float*)d_in[2];
    const float* b1   = (const float*)d_in[3];
    const float* W2   = (const float*)d_in[4];
    const float* b2   = (const float*)d_in[5];
    const float* Wlin = (const float*)d_in[6];
    const float* blin = (const float*)d_in[7];

    const int FIN = in_sizes[2] / HDIM;   // 128
    const int n   = in_sizes[0] / FIN;    // 100000
    const int e   = in_sizes[1] / 2;      // 3200000

    float* hbuf;  cudaGetSymbolAddress((void**)&hbuf, g_h);
    float* abuf;  cudaGetSymbolAddress((void**)&abuf, g_agg);
    int*   cntp;  cudaGetSymbolAddress((void**)&cntp, g_cnt);

    const int T = 256;
    const int nb_n  = (n + T - 1) / T;
    const int nb_e  = (e + T - 1) / T;
    const int nb_w  = (n * 32 + T - 1) / T;          // warp-per-node grids
    const int nb_sb = (n + 1023) / 1024;             // scan blocks (98)

    // ---- build normalization + dst-sorted CSR (once; reused by both layers)
    k_detect<<<1, 32>>>(ei, n);
    cudaMemsetAsync(cntp, 0, (size_t)n * sizeof(int));
    k_convert_hist<<<nb_e, T>>>(ei, e);
    k_scan1<<<nb_sb, T>>>(n);
    k_scan2<<<1, 128>>>(nb_sb, n);
    k_scan3<<<nb_n, T>>>(n);
    k_scatter_idx<<<nb_e, T>>>(e);

    // ---- layer 1: h' = (x @ W1) * dinv ; agg = csr-sum
    k_gemm<128, false><<<1480, dim3(16, 16)>>>(x, W1, nullptr, hbuf, n);
    k_aggregate<<<nb_w, T>>>(n);

    // ---- layer 2: h' = (relu(agg*dinv + b1) @ W2) * dinv ; agg = csr-sum
    k_gemm<64, true><<<1480, dim3(16, 16)>>>(abuf, W2, b1, hbuf, n);
    k_aggregate<<<nb_w, T>>>(n);

    // ---- head
    k_final<<<nb_w, T>>>(b2, Wlin, blin, (float*)d_out, n);
}